// round 16
// baseline (speedup 1.0000x reference)
#include <cuda_runtime.h>
#include <cuda_bf16.h>
#include <cstdint>

#define GH 20        // hidden size
#define GL 5         // layers
#define GT 4096      // timesteps
#define GB 256       // batch
#define GC 16        // chunk (timesteps per superstep)
#define NCHUNK (GT / GC)                 // 256
#define NSUP   (NCHUNK + 2 * (GL - 1))   // 264 (+1 drain superstep in loop)
#define NTHREADS 256                     // 8 warps: 5 rec + 3 inp

using u64 = unsigned long long;
using u32 = unsigned int;

// xp stride: 4 floats per unit -> (r,z,n,pad), one float4
#define XPS 4

// dynamic smem layout (bytes)
// xs: float[GT]; hch: u64 pairs [GL][2][GC][GH]; xpb: float[GL-1][2][GC][GH][XPS]; hlast: float[GL*GH]
#define XS_OFF    0
#define HCH_OFF   (GT * 4)                                    // 16384
#define XPB_OFF   (HCH_OFF + GL * 2 * GC * GH * 8)            // +25600 = 41984
#define HLAST_OFF (XPB_OFF + (GL - 1) * 2 * GC * GH * XPS * 4) // +40960 = 82944
#define SMEM_SZ   (HLAST_OFF + GL * GH * 4 + 16)              // 83360

#define C1 (-1.4426950408889634f)   // -log2(e)
#define C2 (-2.8853900817779268f)   // -2*log2(e)

struct GruParams {
    const float* x;
    const float* Wih[GL];
    const float* Whh[GL];
    const float* bih[GL];
    const float* bhh[GL];
    const float* Wout;
    const float* bout;
    float* out_h;
    float* out_hn;
    float* out_y;
};

// ---------- packed f32x2 helpers ----------
__device__ __forceinline__ u64 pack2(float lo, float hi) {
    u64 r; asm("mov.b64 %0, {%1,%2};" : "=l"(r) : "f"(lo), "f"(hi)); return r;
}
__device__ __forceinline__ void unpack2(u64 v, float& a, float& b) {
    asm("mov.b64 {%0,%1}, %2;" : "=f"(a), "=f"(b) : "l"(v));
}
__device__ __forceinline__ float lo32f(u64 v) {
    return __uint_as_float((u32)v);   // low half = first packed float
}
__device__ __forceinline__ u64 fma2(u64 a, u64 b, u64 c) {
    u64 d; asm("fma.rn.f32x2 %0, %1, %2, %3;" : "=l"(d) : "l"(a), "l"(b), "l"(c)); return d;
}
__device__ __forceinline__ u64 add2(u64 a, u64 b) {
    u64 d; asm("add.rn.f32x2 %0, %1, %2;" : "=l"(d) : "l"(a), "l"(b)); return d;
}

// ---------- predication / smem helpers ----------
__device__ __forceinline__ void sts64_pred(u32 addr, u64 v, int pred) {
    asm volatile("{ .reg .pred p; setp.ne.s32 p, %2, 0; @p st.shared.b64 [%0], %1; }"
                 :: "r"(addr), "l"(v), "r"(pred) : "memory");
}
__device__ __forceinline__ void sts128_pred4(u32 addr, float v0, float v1, float v2, float v3, int pred) {
    asm volatile("{ .reg .pred p; setp.ne.s32 p, %5, 0; @p st.shared.v4.f32 [%0], {%1,%2,%3,%4}; }"
                 :: "r"(addr), "f"(v0), "f"(v1), "f"(v2), "f"(v3), "r"(pred) : "memory");
}
__device__ __forceinline__ float selpf(float a, float b, int c) {
    float r;
    asm("{ .reg .pred p; setp.ne.s32 p, %3, 0; selp.f32 %0, %1, %2, p; }"
        : "=f"(r) : "f"(a), "f"(b), "r"(c));
    return r;
}
__device__ __forceinline__ u32 smem_addr(const void* p) {
    return (u32)__cvta_generic_to_shared(p);
}

// ---------- fast activations (args pre-scaled by C1/C2) ----------
__device__ __forceinline__ float fast_exp2(float x) {
    float r; asm("ex2.approx.f32 %0, %1;" : "=f"(r) : "f"(x)); return r;
}
__device__ __forceinline__ float fast_rcp(float x) {
    float r; asm("rcp.approx.f32 %0, %1;" : "=f"(r) : "f"(x)); return r;
}

// Rec role: w01[k] = pack2(C1*Whh[rowA][k], sB*Whh[rowB][k]); bAB likewise.
// Inp role: wrz[k] = pack2(C1*Wih[r_i][k], C1*Wih[z_i][k]); wn[k] = C2*Wih[n_i][k].
struct RecW {
    u64 w01[GH];       // rec: packed (rowA, rowB)   | inp: packed (r,z) rows
    float wn[GH];      // inp only: n row
    u64 bAB;           // rec packed bias            | inp packed (r,z) bias
    float bn;          // inp n bias
    float c0r, c0z, c0n, bx0, bx1, bx2;  // layer-0 input path (prescaled)
};

// One GRU step. hrow points at packed (h,h) pairs for t-1.
template <bool L0>
__device__ __forceinline__ float rec_body(const RecW& W, float hu,
                                          const u64* hrow,
                                          const float* xpt, const float* xs_t,
                                          int ii, int uz1, int uz2, int un, int selz) {
    // x inputs (prescaled)
    float xr, xz, xn;
    if (L0) {
        const float xt = *xs_t;
        xr = fmaf(W.c0r, xt, W.bx0);
        xz = fmaf(W.c0z, xt, W.bx1);
        xn = fmaf(W.c0n, xt, W.bx2);
    } else {
        float4 v = *(const float4*)(xpt + (size_t)ii * XPS);
        xr = v.x; xz = v.y; xn = v.z;
    }

    // packed dual-row dot: lane computes rowA (r/z region) and rowB simultaneously
    u64 a = W.bAB, s = 0;
    const ulonglong2* h2 = (const ulonglong2*)hrow;
#pragma unroll
    for (int q = 0; q < GH / 2; q++) {
        const ulonglong2 v = h2[q];
        a = fma2(W.w01[2 * q],     v.x, a);
        s = fma2(W.w01[2 * q + 1], v.y, s);
    }
    a = add2(a, s);
    float aA, aB;
    unpack2(a, aA, aB);

    // regroup to unit-per-lane (rows: u=lane for r; 20+u for z; 40+u for n)
    const float azA = __shfl_sync(0xffffffffu, aA, uz1);
    const float azB = __shfl_sync(0xffffffffu, aB, uz2);
    const float an  = __shfl_sync(0xffffffffu, aB, un);
    const float az  = selpf(azA, azB, selz);

    const float sr = xr + aA;    // prescaled by C1
    const float sz = xz + az;    // prescaled by C1

    // sigmoids via ex2+rcp (prescaled args); tanh arm prescaled by C2
    const float ea  = fast_exp2(sr);
    const float r   = fast_rcp(1.0f + ea);
    const float eb  = fast_exp2(sz);
    const float z   = fast_rcp(1.0f + eb);
    const float zh  = z * hu;
    const float omz = 1.0f - z;
    const float t   = fast_exp2(fmaf(r, an, xn));
    const float n   = fmaf(2.0f, fast_rcp(1.0f + t), -1.0f);
    return fmaf(n, omz, zh);
}

// One 16-step chunk for a rec warp.
template <bool L0>
__device__ __forceinline__ float rec_chunk(const RecW& W, float hu,
                                           u64* hb, const u64* hb_prev,
                                           const float* xp, const float* xs, int tbase,
                                           int ii, int pa,
                                           int uz1, int uz2, int un, int selz) {
    const u32 hb_a = smem_addr(hb) + (u32)ii * 8u;

    // tin = 0 (carry from previous chunk's opposite-parity buffer)
    __syncwarp();
    hu = rec_body<L0>(W, hu, hb_prev + (GC - 1) * GH, xp, xs + tbase,
                      ii, uz1, uz2, un, selz);
    sts64_pred(hb_a, pack2(hu, hu), pa);

#pragma unroll 3
    for (int tin = 1; tin < GC; tin++) {
        __syncwarp();
        hu = rec_body<L0>(W, hu, hb + (tin - 1) * GH,
                          xp + (size_t)tin * GH * XPS, xs + tbase + tin,
                          ii, uz1, uz2, un, selz);
        sts64_pred(hb_a + (u32)(tin * GH) * 8u, pack2(hu, hu), pa);
    }
    return hu;
}

__global__ __launch_bounds__(NTHREADS, 2) void gru_packed_rows_kernel(GruParams p) {
    extern __shared__ __align__(16) unsigned char sm[];
    float* xs    = (float*)(sm + XS_OFF);    // [GT]
    u64*   hch   = (u64*)(sm + HCH_OFF);     // [GL][2][GC][GH] packed (h,h)
    float* xpb   = (float*)(sm + XPB_OFF);   // [GL-1][2][GC][GH][XPS]
    float* hlast = (float*)(sm + HLAST_OFF); // [GL*GH]

    const int tid  = threadIdx.x;
    const int wid  = tid >> 5;
    const int lane = tid & 31;
    const int b    = blockIdx.x;

    const float* xsrc = p.x + (size_t)b * GT;
    for (int t = tid; t < GT; t += NTHREADS) xs[t] = xsrc[t];
    for (int q = tid; q < GL * 2 * GC * GH; q += NTHREADS) hch[q] = 0ull;

    // ---- roles ----
    const bool isRec = (wid < GL);
    int l, i;
    bool act;
    if (isRec) { l = wid; i = lane; act = (lane < GH); }
    else {
        int idx = (wid - GL) * 32 + lane;          // 0..95
        act = (idx < (GL - 1) * GH);               // 80 tasks
        l = act ? 1 + idx / GH : 1;
        i = act ? idx % GH : 0;
    }
    const int ii = (i < GH) ? i : 0;
    const int pa = act ? 1 : 0;

    // shuffle regroup constants (rec role)
    const int uz1  = (20 + ii < 32) ? (20 + ii) : 31;
    const int uz2  = (ii - 12 > 0) ? (ii - 12) : 0;
    const int un   = 8 + ii;
    const int selz = (ii < 12) ? 1 : 0;

    // ---- weights (prescaled, packed) ----
    RecW W;
    W.bAB = 0; W.bn = 0.f;
    W.c0r = W.c0z = W.c0n = W.bx0 = W.bx1 = W.bx2 = 0.f;
#pragma unroll
    for (int k = 0; k < GH; k++) { W.w01[k] = 0; W.wn[k] = 0.f; }

    if (isRec) {
        const float* Wh = p.Whh[l];
        const int rowA = lane;                               // rows 0-31: r/z -> C1
        const int rowB = (32 + lane < 60) ? (32 + lane) : 59;
        const float sB = (rowB < 2 * GH) ? C1 : C2;          // z rows C1, n rows C2
#pragma unroll
        for (int k = 0; k < GH; k++)
            W.w01[k] = pack2(C1 * Wh[rowA * GH + k], sB * Wh[rowB * GH + k]);
        W.bAB = pack2(C1 * p.bhh[l][rowA], sB * p.bhh[l][rowB]);
        if (l == 0) {
            const float* Wi = p.Wih[0];
            W.c0r = C1 * Wi[ii];
            W.c0z = C1 * Wi[GH + ii];
            W.c0n = C2 * Wi[2 * GH + ii];
            W.bx0 = C1 * p.bih[0][ii];
            W.bx1 = C1 * p.bih[0][GH + ii];
            W.bx2 = C2 * p.bih[0][2 * GH + ii];
        }
    } else if (act) {
        const float* Wi = p.Wih[l];
#pragma unroll
        for (int k = 0; k < GH; k++) {
            W.w01[k] = pack2(C1 * Wi[(i) * GH + k], C1 * Wi[(GH + i) * GH + k]);
            W.wn[k]  = C2 * Wi[(2 * GH + i) * GH + k];
        }
        W.bAB = pack2(C1 * p.bih[l][i], C1 * p.bih[l][GH + i]);
        W.bn  = C2 * p.bih[l][2 * GH + i];
    }

    float* outrow = p.out_h + (size_t)b * GT * GH;

    float hu = 0.f;

    __syncthreads();

    // ---- superstep pipeline (+1 drain step for the out-copy stage) ----
    for (int S = 0; S < NSUP + 1; S++) {
        const int par = S & 1;

        if (isRec) {
            const int c = S - 2 * l;
            if ((unsigned)c < (unsigned)NCHUNK) {
                u64* hb            = hch + (size_t)(l * 2 + par) * GC * GH;
                const u64* hb_prev = hch + (size_t)(l * 2 + (par ^ 1)) * GC * GH;
                const float* xp    = xpb + (size_t)((l - 1) * 2 + (par ^ 1)) * GC * GH * XPS;
                const int tbase = c * GC;

                if (l == 0)
                    hu = rec_chunk<true>(W, hu, hb, hb_prev, xp, xs, tbase, ii, pa,
                                         uz1, uz2, un, selz);
                else
                    hu = rec_chunk<false>(W, hu, hb, hb_prev, xp, xs, tbase, ii, pa,
                                          uz1, uz2, un, selz);

                if (act && c == NCHUNK - 1) hlast[l * GH + ii] = hu;
            }
        } else {
            const int c = S - (2 * l - 1);
            if ((unsigned)c < (unsigned)NCHUNK) {
                const u64* hsrc = hch + (size_t)((l - 1) * 2 + (par ^ 1)) * GC * GH;
                float* dst = xpb + (size_t)((l - 1) * 2 + par) * GC * GH * XPS;
                const u32 dst_a = smem_addr(dst) + (u32)ii * (XPS * 4u);

#pragma unroll 2
                for (int tin = 0; tin < GC; tin++) {
                    const ulonglong2* h2 = (const ulonglong2*)(hsrc + tin * GH);

                    // packed (r,z) chain + scalar n chain sharing the same loads
                    u64 arz = W.bAB, srz = 0;
                    float an = W.bn, sn = 0.f;
#pragma unroll
                    for (int q = 0; q < GH / 2; q++) {
                        const ulonglong2 v = h2[q];
                        arz = fma2(W.w01[2 * q],     v.x, arz);
                        srz = fma2(W.w01[2 * q + 1], v.y, srz);
                        an  = fmaf(W.wn[2 * q],     lo32f(v.x), an);
                        sn  = fmaf(W.wn[2 * q + 1], lo32f(v.y), sn);
                    }
                    arz = add2(arz, srz);
                    float ar, az;
                    unpack2(arz, ar, az);

                    const u32 base = dst_a + (u32)(tin * GH * XPS) * 4u;
                    sts128_pred4(base, ar, az, an + sn, 0.0f, pa);
                }
            }

            // out-copy stage (wid 7): stream layer-4's finished chunk to GMEM
            if (wid == 7) {
                const int cc = S - (2 * (GL - 1) + 1);   // chunk written at S-1
                if ((unsigned)cc < (unsigned)NCHUNK) {
                    const u64* src = hch + (size_t)((GL - 1) * 2 + (par ^ 1)) * GC * GH;
                    float* dstg = outrow + (size_t)cc * GC * GH;   // 320 contiguous floats
#pragma unroll
                    for (int q = 0; q < (GC * GH) / 32; q++) {     // 10 iters, coalesced
                        const int idx = q * 32 + lane;
                        dstg[idx] = lo32f(src[idx]);
                    }
                }
            }
        }
        __syncthreads();
    }

    // ---- epilogue ----
    if (tid < GL * GH)
        p.out_hn[(size_t)b * GL * GH + tid] = hlast[tid];

    if (wid == 0) {
        float acc = 0.f;
        for (int j = lane; j < GL * GH; j += 32)
            acc = fmaf(p.Wout[j], hlast[j], acc);
#pragma unroll
        for (int off = 16; off; off >>= 1)
            acc += __shfl_xor_sync(0xffffffffu, acc, off);
        if (lane == 0)
            p.out_y[b] = acc + p.bout[0];
    }
}

extern "C" void kernel_launch(void* const* d_in, const int* in_sizes, int n_in,
                              void* d_out, int out_size) {
    (void)in_sizes; (void)n_in; (void)out_size;

    GruParams p;
    p.x = (const float*)d_in[0];
    for (int l = 0; l < GL; l++) {
        p.Wih[l] = (const float*)d_in[1 + 4 * l + 0];
        p.Whh[l] = (const float*)d_in[1 + 4 * l + 1];
        p.bih[l] = (const float*)d_in[1 + 4 * l + 2];
        p.bhh[l] = (const float*)d_in[1 + 4 * l + 3];
    }
    p.Wout = (const float*)d_in[21];
    p.bout = (const float*)d_in[22];

    float* out = (float*)d_out;
    p.out_h  = out;
    p.out_hn = out + (size_t)GB * GT * GH;
    p.out_y  = out + (size_t)GB * GT * GH + (size_t)GB * GL * GH;

    cudaFuncSetAttribute(gru_packed_rows_kernel,
                         cudaFuncAttributeMaxDynamicSharedMemorySize, SMEM_SZ);
    gru_packed_rows_kernel<<<GB, NTHREADS, SMEM_SZ>>>(p);
}

// round 17
// speedup vs baseline: 1.0738x; 1.0738x over previous
#include <cuda_runtime.h>
#include <cuda_bf16.h>
#include <cstdint>

#define GH 20        // hidden size
#define GL 5         // layers
#define GT 4096      // timesteps
#define GB 256       // batch
#define GC 16        // chunk (timesteps per superstep)
#define NCHUNK (GT / GC)                 // 256
#define NSUP   (NCHUNK + 2 * (GL - 1))   // 264 (+1 drain superstep in loop)
#define NTHREADS 256                     // 8 warps: 5 rec + 3 inp

using u64 = unsigned long long;
using u32 = unsigned int;

// xp stride: 4 floats per unit -> (r,z,n,pad), one float4
#define XPS 4

// dynamic smem layout (bytes) — scalar floats (identical to R12)
#define XS_OFF    0
#define HCH_OFF   (GT * 4)                                   // 16384
#define XPB_OFF   (HCH_OFF + GL * 2 * GC * GH * 4)           // +12800 = 29184
#define HLAST_OFF (XPB_OFF + (GL - 1) * 2 * GC * GH * XPS * 4) // +40960 = 70144
#define SMEM_SZ   (HLAST_OFF + GL * GH * 4 + 16)             // ~70560

#define C1 (-1.4426950408889634f)   // -log2(e)
#define C2 (-2.8853900817779268f)   // -2*log2(e)

struct GruParams {
    const float* x;
    const float* Wih[GL];
    const float* Whh[GL];
    const float* bih[GL];
    const float* bhh[GL];
    const float* Wout;
    const float* bout;
    float* out_h;
    float* out_hn;
    float* out_y;
};

// ---------- packed f32x2 helpers ----------
__device__ __forceinline__ u64 pack2(float lo, float hi) {
    u64 r; asm("mov.b64 %0, {%1,%2};" : "=l"(r) : "f"(lo), "f"(hi)); return r;
}
__device__ __forceinline__ void unpack2(u64 v, float& a, float& b) {
    asm("mov.b64 {%0,%1}, %2;" : "=f"(a), "=f"(b) : "l"(v));
}
__device__ __forceinline__ u64 fma2(u64 a, u64 b, u64 c) {
    u64 d; asm("fma.rn.f32x2 %0, %1, %2, %3;" : "=l"(d) : "l"(a), "l"(b), "l"(c)); return d;
}
__device__ __forceinline__ u64 add2(u64 a, u64 b) {
    u64 d; asm("add.rn.f32x2 %0, %1, %2;" : "=l"(d) : "l"(a), "l"(b)); return d;
}
__device__ __forceinline__ float hadd2(u64 v) {
    float a, b; unpack2(v, a, b); return a + b;
}

// ---------- predication / smem helpers ----------
__device__ __forceinline__ void sts32_pred(u32 addr, float v, int pred) {
    asm volatile("{ .reg .pred p; setp.ne.s32 p, %2, 0; @p st.shared.f32 [%0], %1; }"
                 :: "r"(addr), "f"(v), "r"(pred) : "memory");
}
__device__ __forceinline__ void sts128_pred4(u32 addr, float v0, float v1, float v2, float v3, int pred) {
    asm volatile("{ .reg .pred p; setp.ne.s32 p, %5, 0; @p st.shared.v4.f32 [%0], {%1,%2,%3,%4}; }"
                 :: "r"(addr), "f"(v0), "f"(v1), "f"(v2), "f"(v3), "r"(pred) : "memory");
}
__device__ __forceinline__ float selpf(float a, float b, int c) {
    float r;
    asm("{ .reg .pred p; setp.ne.s32 p, %3, 0; selp.f32 %0, %1, %2, p; }"
        : "=f"(r) : "f"(a), "f"(b), "r"(c));
    return r;
}
__device__ __forceinline__ u32 smem_addr(const void* p) {
    return (u32)__cvta_generic_to_shared(p);
}

// ---------- fast activations (args pre-scaled by C1/C2) ----------
__device__ __forceinline__ float fast_exp2(float x) {
    float r; asm("ex2.approx.f32 %0, %1;" : "=f"(r) : "f"(x)); return r;
}
__device__ __forceinline__ float fast_rcp(float x) {
    float r; asm("rcp.approx.f32 %0, %1;" : "=f"(r) : "f"(x)); return r;
}

// k-packed weights: wA[q] = pack2(w[2q], w[2q+1]) of prescaled row.
// Rec: wA = rowA (r-region), wB = rowB. Inp: wA/wB/wC = r/z/n rows.
struct RecW {
    u64 wA[GH / 2], wB[GH / 2], wC[GH / 2];
    float bA, bB;                        // rec pass biases (prescaled)
    float bias0, bias1, bias2;           // inp biases (prescaled)
    float c0r, c0z, c0n, bx0, bx1, bx2;  // layer-0 input path (prescaled)
};

// One GRU step. hrow: scalar float row (16B-aligned), read as packed pairs.
template <bool L0>
__device__ __forceinline__ float rec_body(const RecW& W, float hu,
                                          const float* hrow,
                                          const float* xpt, const float* xs_t,
                                          int ii, int uz1, int uz2, int un, int selz) {
    // x inputs (prescaled)
    float xr, xz, xn;
    if (L0) {
        const float xt = *xs_t;
        xr = fmaf(W.c0r, xt, W.bx0);
        xz = fmaf(W.c0z, xt, W.bx1);
        xn = fmaf(W.c0n, xt, W.bx2);
    } else {
        float4 v = *(const float4*)(xpt + (size_t)ii * XPS);
        xr = v.x; xz = v.y; xn = v.z;
    }

    // k-packed dual-row dot: 20 fma2 total (2 chains per row, depth 5)
    const ulonglong2* h2 = (const ulonglong2*)hrow;   // 5 × (2 packed pairs)
    u64 aA0 = 0, aA1 = 0, aB0 = 0, aB1 = 0;
#pragma unroll
    for (int q = 0; q < GH / 4; q++) {                // 5 iters
        const ulonglong2 v = h2[q];
        aA0 = fma2(W.wA[2 * q],     v.x, aA0);
        aA1 = fma2(W.wA[2 * q + 1], v.y, aA1);
        aB0 = fma2(W.wB[2 * q],     v.x, aB0);
        aB1 = fma2(W.wB[2 * q + 1], v.y, aB1);
    }
    const float aA = hadd2(add2(aA0, aA1)) + W.bA;
    const float aB = hadd2(add2(aB0, aB1)) + W.bB;

    // regroup to unit-per-lane (rows: u=lane for r; 20+u for z; 40+u for n)
    const float azA = __shfl_sync(0xffffffffu, aA, uz1);
    const float azB = __shfl_sync(0xffffffffu, aB, uz2);
    const float an  = __shfl_sync(0xffffffffu, aB, un);
    const float az  = selpf(azA, azB, selz);

    const float sr = xr + aA;    // prescaled by C1
    const float sz = xz + az;    // prescaled by C1

    // sigmoids via ex2+rcp (prescaled args); tanh arm prescaled by C2
    const float ea  = fast_exp2(sr);
    const float r   = fast_rcp(1.0f + ea);
    const float eb  = fast_exp2(sz);
    const float z   = fast_rcp(1.0f + eb);
    const float zh  = z * hu;
    const float omz = 1.0f - z;
    const float t   = fast_exp2(fmaf(r, an, xn));
    const float n   = fmaf(2.0f, fast_rcp(1.0f + t), -1.0f);
    return fmaf(n, omz, zh);
}

// One 16-step chunk for a rec warp.
template <bool L0>
__device__ __forceinline__ float rec_chunk(const RecW& W, float hu,
                                           float* hb, const float* hb_prev,
                                           const float* xp, const float* xs, int tbase,
                                           int ii, int pa,
                                           int uz1, int uz2, int un, int selz) {
    const u32 hb_a = smem_addr(hb) + (u32)ii * 4u;

    // tin = 0 (carry from previous chunk's opposite-parity buffer)
    __syncwarp();
    hu = rec_body<L0>(W, hu, hb_prev + (GC - 1) * GH, xp, xs + tbase,
                      ii, uz1, uz2, un, selz);
    sts32_pred(hb_a, hu, pa);

#pragma unroll 3
    for (int tin = 1; tin < GC; tin++) {
        __syncwarp();
        hu = rec_body<L0>(W, hu, hb + (tin - 1) * GH,
                          xp + (size_t)tin * GH * XPS, xs + tbase + tin,
                          ii, uz1, uz2, un, selz);
        sts32_pred(hb_a + (u32)(tin * GH) * 4u, hu, pa);
    }
    return hu;
}

__global__ __launch_bounds__(NTHREADS, 2) void gru_kpacked_kernel(GruParams p) {
    extern __shared__ __align__(16) unsigned char sm[];
    float* xs    = (float*)(sm + XS_OFF);    // [GT] x for this batch
    float* hch   = (float*)(sm + HCH_OFF);   // [GL][2][GC][GH]
    float* xpb   = (float*)(sm + XPB_OFF);   // [GL-1][2][GC][GH][XPS]
    float* hlast = (float*)(sm + HLAST_OFF); // [GL*GH]

    const int tid  = threadIdx.x;
    const int wid  = tid >> 5;
    const int lane = tid & 31;
    const int b    = blockIdx.x;

    const float* xsrc = p.x + (size_t)b * GT;
    for (int t = tid; t < GT; t += NTHREADS) xs[t] = xsrc[t];
    for (int q = tid; q < GL * 2 * GC * GH; q += NTHREADS) hch[q] = 0.0f;

    // ---- roles ----
    const bool isRec = (wid < GL);
    int l, i;
    bool act;
    if (isRec) { l = wid; i = lane; act = (lane < GH); }
    else {
        int idx = (wid - GL) * 32 + lane;          // 0..95
        act = (idx < (GL - 1) * GH);               // 80 tasks
        l = act ? 1 + idx / GH : 1;
        i = act ? idx % GH : 0;
    }
    const int ii = (i < GH) ? i : 0;
    const int pa = act ? 1 : 0;

    // shuffle regroup constants (rec role)
    const int uz1  = (20 + ii < 32) ? (20 + ii) : 31;
    const int uz2  = (ii - 12 > 0) ? (ii - 12) : 0;
    const int un   = 8 + ii;
    const int selz = (ii < 12) ? 1 : 0;

    // ---- weights (prescaled, k-packed) ----
    RecW W;
    W.bA = W.bB = 0.f;
    W.bias0 = W.bias1 = W.bias2 = 0.f;
    W.c0r = W.c0z = W.c0n = W.bx0 = W.bx1 = W.bx2 = 0.f;
#pragma unroll
    for (int q = 0; q < GH / 2; q++) { W.wA[q] = 0; W.wB[q] = 0; W.wC[q] = 0; }

    if (isRec) {
        const float* Wh = p.Whh[l];
        const int rowA = lane;                               // rows 0-31: r/z -> C1
        const int rowB = (32 + lane < 60) ? (32 + lane) : 59;
        const float sB = (rowB < 2 * GH) ? C1 : C2;          // z rows C1, n rows C2
#pragma unroll
        for (int q = 0; q < GH / 2; q++) {
            W.wA[q] = pack2(C1 * Wh[rowA * GH + 2 * q], C1 * Wh[rowA * GH + 2 * q + 1]);
            W.wB[q] = pack2(sB * Wh[rowB * GH + 2 * q], sB * Wh[rowB * GH + 2 * q + 1]);
        }
        W.bA = C1 * p.bhh[l][rowA];
        W.bB = sB * p.bhh[l][rowB];
        if (l == 0) {
            const float* Wi = p.Wih[0];
            W.c0r = C1 * Wi[ii];
            W.c0z = C1 * Wi[GH + ii];
            W.c0n = C2 * Wi[2 * GH + ii];
            W.bx0 = C1 * p.bih[0][ii];
            W.bx1 = C1 * p.bih[0][GH + ii];
            W.bx2 = C2 * p.bih[0][2 * GH + ii];
        }
    } else if (act) {
        const float* Wi = p.Wih[l];
#pragma unroll
        for (int q = 0; q < GH / 2; q++) {
            W.wA[q] = pack2(C1 * Wi[(i) * GH + 2 * q],          C1 * Wi[(i) * GH + 2 * q + 1]);
            W.wB[q] = pack2(C1 * Wi[(GH + i) * GH + 2 * q],     C1 * Wi[(GH + i) * GH + 2 * q + 1]);
            W.wC[q] = pack2(C2 * Wi[(2 * GH + i) * GH + 2 * q], C2 * Wi[(2 * GH + i) * GH + 2 * q + 1]);
        }
        W.bias0 = C1 * p.bih[l][i];
        W.bias1 = C1 * p.bih[l][GH + i];
        W.bias2 = C2 * p.bih[l][2 * GH + i];
    }

    float* outrow = p.out_h + (size_t)b * GT * GH;

    float hu = 0.f;

    __syncthreads();

    // ---- superstep pipeline (+1 drain step for the out-copy stage) ----
    for (int S = 0; S < NSUP + 1; S++) {
        const int par = S & 1;

        if (isRec) {
            const int c = S - 2 * l;
            if ((unsigned)c < (unsigned)NCHUNK) {
                float* hb            = hch + (size_t)(l * 2 + par) * GC * GH;
                const float* hb_prev = hch + (size_t)(l * 2 + (par ^ 1)) * GC * GH;
                const float* xp      = xpb + (size_t)((l - 1) * 2 + (par ^ 1)) * GC * GH * XPS;
                const int tbase = c * GC;

                if (l == 0)
                    hu = rec_chunk<true>(W, hu, hb, hb_prev, xp, xs, tbase, ii, pa,
                                         uz1, uz2, un, selz);
                else
                    hu = rec_chunk<false>(W, hu, hb, hb_prev, xp, xs, tbase, ii, pa,
                                          uz1, uz2, un, selz);

                if (act && c == NCHUNK - 1) hlast[l * GH + ii] = hu;
            }
        } else {
            const int c = S - (2 * l - 1);
            if ((unsigned)c < (unsigned)NCHUNK) {
                const float* hsrc = hch + (size_t)((l - 1) * 2 + (par ^ 1)) * GC * GH;
                float* dst = xpb + (size_t)((l - 1) * 2 + par) * GC * GH * XPS;
                const u32 dst_a = smem_addr(dst) + (u32)ii * (XPS * 4u);

#pragma unroll 2
                for (int tin = 0; tin < GC; tin++) {
                    const ulonglong2* h2 = (const ulonglong2*)(hsrc + tin * GH);

                    u64 a0 = 0, s0 = 0, a1 = 0, s1 = 0, a2 = 0, s2 = 0;
#pragma unroll
                    for (int q = 0; q < GH / 4; q++) {   // 5 iters, 30 fma2 total
                        const ulonglong2 v = h2[q];
                        a0 = fma2(W.wA[2 * q],     v.x, a0);
                        s0 = fma2(W.wA[2 * q + 1], v.y, s0);
                        a1 = fma2(W.wB[2 * q],     v.x, a1);
                        s1 = fma2(W.wB[2 * q + 1], v.y, s1);
                        a2 = fma2(W.wC[2 * q],     v.x, a2);
                        s2 = fma2(W.wC[2 * q + 1], v.y, s2);
                    }
                    const float ar = hadd2(add2(a0, s0)) + W.bias0;
                    const float az = hadd2(add2(a1, s1)) + W.bias1;
                    const float an = hadd2(add2(a2, s2)) + W.bias2;

                    const u32 base = dst_a + (u32)(tin * GH * XPS) * 4u;
                    sts128_pred4(base, ar, az, an, 0.0f, pa);
                }
            }

            // out-copy stage (wid 7): stream layer-4's finished chunk to GMEM
            if (wid == 7) {
                const int cc = S - (2 * (GL - 1) + 1);   // chunk written at S-1
                if ((unsigned)cc < (unsigned)NCHUNK) {
                    const float* src = hch + (size_t)((GL - 1) * 2 + (par ^ 1)) * GC * GH;
                    float* dstg = outrow + (size_t)cc * GC * GH;   // 320 contiguous floats
#pragma unroll
                    for (int q = 0; q < (GC * GH) / 32; q++) {     // 10 iters, coalesced
                        const int idx = q * 32 + lane;
                        dstg[idx] = src[idx];
                    }
                }
            }
        }
        __syncthreads();
    }

    // ---- epilogue ----
    if (tid < GL * GH)
        p.out_hn[(size_t)b * GL * GH + tid] = hlast[tid];

    if (wid == 0) {
        float acc = 0.f;
        for (int j = lane; j < GL * GH; j += 32)
            acc = fmaf(p.Wout[j], hlast[j], acc);
#pragma unroll
        for (int off = 16; off; off >>= 1)
            acc += __shfl_xor_sync(0xffffffffu, acc, off);
        if (lane == 0)
            p.out_y[b] = acc + p.bout[0];
    }
}

extern "C" void kernel_launch(void* const* d_in, const int* in_sizes, int n_in,
                              void* d_out, int out_size) {
    (void)in_sizes; (void)n_in; (void)out_size;

    GruParams p;
    p.x = (const float*)d_in[0];
    for (int l = 0; l < GL; l++) {
        p.Wih[l] = (const float*)d_in[1 + 4 * l + 0];
        p.Whh[l] = (const float*)d_in[1 + 4 * l + 1];
        p.bih[l] = (const float*)d_in[1 + 4 * l + 2];
        p.bhh[l] = (const float*)d_in[1 + 4 * l + 3];
    }
    p.Wout = (const float*)d_in[21];
    p.bout = (const float*)d_in[22];

    float* out = (float*)d_out;
    p.out_h  = out;
    p.out_hn = out + (size_t)GB * GT * GH;
    p.out_y  = out + (size_t)GB * GT * GH + (size_t)GB * GL * GH;

    cudaFuncSetAttribute(gru_kpacked_kernel,
                         cudaFuncAttributeMaxDynamicSharedMemorySize, SMEM_SZ);
    gru_kpacked_kernel<<<GB, NTHREADS, SMEM_SZ>>>(p);
}